// round 15
// baseline (speedup 1.0000x reference)
#include <cuda_runtime.h>
#include <cuda_fp16.h>

// ---------------------------------------------------------------------------
// Fused BN -> sign(+-1) -> 3x3 conv -> bias -> ReLU, fp16 tensor-core
// implicit GEMM. Persistent CTAs, warp-specialized (R12 structure):
//   warps 0-3: MMA (2 rows x 32 px x 32 co) + in-warp transpose epilogue
//   warps 4-7: build next tile concurrently (4-deep LDG pipeline).
// R15: contiguous y-chunk tile walk (halo rows L2-hot, -25% DRAM reads).
// 2 CTAs/SM. Tile: 8 rows x 32 px x 32 co.
// ---------------------------------------------------------------------------

#define HW      65536
#define C_CH    32

#define QROWS   10           // 8 + 2 halo
#define QPX     34           // 32 + 2 halo
#define CIP     40           // ci stride (halfs) -> 80B px stride, ldsm-safe
#define QTILE   (QROWS * QPX * CIP)   // 13600 halfs
#define NWF4    (9 * 2 * 2 * 32)      // 1152 uint4 weight frag pairs
#define SCRW    40                    // scratch px stride (floats)

#define OFF_Q0  0
#define OFF_Q1  (QTILE * 2)
#define OFF_WF  (QTILE * 4)            // 54400
#define OFF_SI  (OFF_WF + NWF4 * 16)   // 72832 : sinvf float[32]
#define OFF_SS  (OFF_SI + 128)         // sshf  float[32]
#define OFF_SB  (OFF_SS + 128)         // sbias float[32]
#define OFF_SCR (OFF_SB + 128)         // 73344 : 4 warps x 32co x 40 floats
#define SMEM_BYTES (OFF_SCR + 4 * 32 * SCRW * 4)   // 93824

#define NT      256
#define NCTA    296                    // 2 per SM x 148
#define NTILES  4096                   // 16 b x 8 xstrip x 32 y (y fastest)
#define CHUNK   14                     // ceil(4096/296)

__device__ __forceinline__ void ldsm_x4(unsigned &a0, unsigned &a1,
                                        unsigned &a2, unsigned &a3,
                                        unsigned addr) {
    asm volatile("ldmatrix.sync.aligned.m8n8.x4.shared.b16 {%0,%1,%2,%3}, [%4];"
                 : "=r"(a0), "=r"(a1), "=r"(a2), "=r"(a3) : "r"(addr));
}
__device__ __forceinline__ void mma16816(float &c0, float &c1, float &c2, float &c3,
                                         unsigned a0, unsigned a1, unsigned a2, unsigned a3,
                                         unsigned b0, unsigned b1) {
    asm volatile("mma.sync.aligned.m16n8k16.row.col.f32.f16.f16.f32 "
                 "{%0,%1,%2,%3},{%4,%5,%6,%7},{%8,%9},{%0,%1,%2,%3};"
                 : "+f"(c0), "+f"(c1), "+f"(c2), "+f"(c3)
                 : "r"(a0), "r"(a1), "r"(a2), "r"(a3), "r"(b0), "r"(b1));
}
__device__ __forceinline__ unsigned pk2(float f0, float iv0, float sh0,
                                        float f1, float iv1, float sh1, bool ok) {
    unsigned lo = ok ? (fmaf(f0, iv0, sh0) > 0.f ? 0x3C00u : 0xBC00u) : 0u;
    unsigned hi = ok ? (fmaf(f1, iv1, sh1) > 0.f ? 0x3C00u : 0xBC00u) : 0u;
    return lo | (hi << 16);
}
__device__ __forceinline__ void sts128(unsigned addr, uint4 v) {
    asm volatile("st.shared.v4.b32 [%0], {%1,%2,%3,%4};"
                 :: "r"(addr), "r"(v.x), "r"(v.y), "r"(v.z), "r"(v.w));
}

// load one body row-group: 8 ci (group g) x 32 px for stored row r
__device__ __forceinline__ void ldrow(const float* __restrict__ xb,
                                      int by, int bx, int r, int g, int lane,
                                      float* F) {
    int gy = by + r - 1;
    bool ok = (unsigned)gy < 256u;
#pragma unroll
    for (int j = 0; j < 8; ++j) F[j] = 0.f;
    if (ok) {
        const float* p = xb + (size_t)(g * 8) * HW + (gy << 8) + bx + lane;
#pragma unroll
        for (int j = 0; j < 8; ++j) F[j] = __ldg(p + (size_t)j * HW);
    }
}
__device__ __forceinline__ void strow(unsigned qn, int by, int r, int g, int lane,
                                      const float* ivr, const float* shr,
                                      const float* F) {
    bool ok = (unsigned)(by + r - 1) < 256u;
    uint4 v;
    v.x = pk2(F[0], ivr[0], shr[0], F[1], ivr[1], shr[1], ok);
    v.y = pk2(F[2], ivr[2], shr[2], F[3], ivr[3], shr[3], ok);
    v.z = pk2(F[4], ivr[4], shr[4], F[5], ivr[5], shr[5], ok);
    v.w = pk2(F[6], ivr[6], shr[6], F[7], ivr[7], shr[7], ok);
    sts128(qn + (((r * QPX + lane + 1) * CIP + g * 8) << 1), v);
}
// halo item ht in [0,80): (r 0..9, side 0..1, oct 0..3), px 0 or 33
__device__ __forceinline__ void halo_item(unsigned qn, const float* __restrict__ xb,
                                          int by, int bx, int ht,
                                          const float* sinvf, const float* sshf) {
    if (ht >= 80) return;
    int r = ht >> 3, side = (ht >> 2) & 1, oct = ht & 3;
    int px = side ? 33 : 0;
    int gy = by + r - 1, gx = bx + px - 1;
    bool ok = ((unsigned)gy < 256u) & ((unsigned)gx < 256u);
    float f[8];
#pragma unroll
    for (int j = 0; j < 8; ++j) f[j] = 0.f;
    if (ok) {
        const float* p = xb + (size_t)(oct * 8) * HW + (gy << 8) + gx;
#pragma unroll
        for (int j = 0; j < 8; ++j) f[j] = __ldg(p + (size_t)j * HW);
    }
    const float* iv = sinvf + oct * 8;
    const float* sh = sshf + oct * 8;
    uint4 v;
    v.x = pk2(f[0], iv[0], sh[0], f[1], iv[1], sh[1], ok);
    v.y = pk2(f[2], iv[2], sh[2], f[3], iv[3], sh[3], ok);
    v.z = pk2(f[4], iv[4], sh[4], f[5], iv[5], sh[5], ok);
    v.w = pk2(f[6], iv[6], sh[6], f[7], iv[7], sh[7], ok);
    sts128(qn + (((r * QPX + px) * CIP + oct * 8) << 1), v);
}

// tile id t -> coords (y fastest within an (batch, x-strip) strip)
__device__ __forceinline__ void tdec(int t, int &b, int &by, int &bx) {
    b  = t >> 8;
    bx = ((t >> 5) & 7) << 5;
    by = (t & 31) << 3;
}

__global__ __launch_bounds__(NT, 2)
void tbconv_chunk_kernel(const float* __restrict__ x,
                         const float* __restrict__ gamma,
                         const float* __restrict__ beta,
                         const float* __restrict__ mean,
                         const float* __restrict__ var,
                         const float* __restrict__ w,
                         const float* __restrict__ bias,
                         float* __restrict__ out)
{
    const int t0  = blockIdx.x * CHUNK;
    const int cnt = min(CHUNK, NTILES - t0);
    if (cnt <= 0) return;

    extern __shared__ char smraw[];
    uint4* wfragsm = (uint4*)(smraw + OFF_WF);
    float* sinvf   = (float*)(smraw + OFF_SI);
    float* sshf    = (float*)(smraw + OFF_SS);
    float* sbias   = (float*)(smraw + OFF_SB);
    float* scratch = (float*)(smraw + OFF_SCR);   // [warp(4)][co(32)][SCRW]

    const int tid  = threadIdx.x;
    const int lane = tid & 31;
    const int wid  = tid >> 5;

    // ---- one-time setup ----
    if (tid < 32) {
        float inv = gamma[tid] * rsqrtf(var[tid] + 1e-4f);
        sinvf[tid] = inv;
        sshf[tid]  = beta[tid] - mean[tid] * inv;
        sbias[tid] = bias[tid];
    }
    // weights pre-shuffled into mma B-fragment order, nt-paired uint4:
    for (int i = tid; i < NWF4; i += NT) {
        int t = i & 31, np = (i >> 5) & 1, s = (i >> 6) & 1, tap = i >> 7;
        int ci = s * 16 + (t & 3) * 2;
        const float* wb0 = w + ((np * 16 + (t >> 2)) * 32 + ci) * 9 + tap;
        const float* wb1 = wb0 + 8 * 32 * 9;
        __half2 lo0 = __floats2half2_rn(wb0[0],  wb0[9]);
        __half2 hi0 = __floats2half2_rn(wb0[72], wb0[81]);
        __half2 lo1 = __floats2half2_rn(wb1[0],  wb1[9]);
        __half2 hi1 = __floats2half2_rn(wb1[72], wb1[81]);
        uint4 v;
        v.x = *(unsigned*)&lo0; v.y = *(unsigned*)&hi0;
        v.z = *(unsigned*)&lo1; v.w = *(unsigned*)&hi1;
        wfragsm[i] = v;
    }

    const unsigned q0a = (unsigned)__cvta_generic_to_shared(smraw) + OFF_Q0;
    const unsigned q1a = q0a + QTILE * 2;

    const int pxl0 = (lane & 7) + ((lane >> 3) & 1) * 8;
    const int cih  = (lane >> 4) * 8;
    const int m0   = lane >> 2;
    const int cb   = (lane & 3) * 2;

    int b, by, bx;
    tdec(t0, b, by, bx);

    __syncthreads();   // setup visible

    // BN constants in registers (used by builders)
    float ivr[8], shr[8];
    {
        int g8 = (wid & 3) * 8;
#pragma unroll
        for (int j = 0; j < 8; ++j) { ivr[j] = sinvf[g8 + j]; shr[j] = sshf[g8 + j]; }
    }

    // ---- prologue: ALL 8 warps build tile 0 into q0 ----
    {
        const float* xb = x + (size_t)b * C_CH * HW;
        int g = wid & 3;
        int rbase = (wid >> 2) * 5;
        float F[8];
#pragma unroll
        for (int k = 0; k < 5; ++k) {
            ldrow(xb, by, bx, rbase + k, g, lane, F);
            strow(q0a, by, rbase + k, g, lane, ivr, shr, F);
        }
        halo_item(q0a, xb, by, bx, tid, sinvf, sshf);
    }
    __syncthreads();

    for (int it = 0; it < cnt; ++it) {
        const unsigned qc = (it & 1) ? q1a : q0a;
        const unsigned qn = (it & 1) ? q0a : q1a;

        const bool hasnext = (it + 1 < cnt);
        int nb = 0, nby = 0, nbx = 0;
        if (hasnext) tdec(t0 + it + 1, nb, nby, nbx);

        if (wid < 4) {
            // ============ MMA role: 2 rows x 32 px x 32 co ============
            const int r0 = wid * 2;
            float acc[2][2][4][4];
#pragma unroll
            for (int rr = 0; rr < 2; ++rr)
#pragma unroll
                for (int mt = 0; mt < 2; ++mt)
#pragma unroll
                    for (int nt = 0; nt < 4; ++nt)
#pragma unroll
                        for (int k = 0; k < 4; ++k) acc[rr][mt][nt][k] = 0.f;

#pragma unroll
            for (int tap = 0; tap < 9; ++tap) {
                const int dy = tap / 3, dx = tap % 3;
#pragma unroll
                for (int S = 0; S < 2; ++S) {
                    uint4 wfa = wfragsm[(((tap * 2 + S) * 2) + 0) * 32 + lane];
                    uint4 wfb = wfragsm[(((tap * 2 + S) * 2) + 1) * 32 + lane];
#pragma unroll
                    for (int rr = 0; rr < 2; ++rr) {
#pragma unroll
                        for (int mt = 0; mt < 2; ++mt) {
                            unsigned a0, a1, a2, a3;
                            unsigned addr = qc +
                                ((((r0 + rr + dy) * QPX + mt * 16 + dx + pxl0) * CIP
                                  + cih + S * 16) << 1);
                            ldsm_x4(a0, a1, a2, a3, addr);
                            mma16816(acc[rr][mt][0][0], acc[rr][mt][0][1],
                                     acc[rr][mt][0][2], acc[rr][mt][0][3],
                                     a0, a1, a2, a3, wfa.x, wfa.y);
                            mma16816(acc[rr][mt][1][0], acc[rr][mt][1][1],
                                     acc[rr][mt][1][2], acc[rr][mt][1][3],
                                     a0, a1, a2, a3, wfa.z, wfa.w);
                            mma16816(acc[rr][mt][2][0], acc[rr][mt][2][1],
                                     acc[rr][mt][2][2], acc[rr][mt][2][3],
                                     a0, a1, a2, a3, wfb.x, wfb.y);
                            mma16816(acc[rr][mt][3][0], acc[rr][mt][3][1],
                                     acc[rr][mt][3][2], acc[rr][mt][3][3],
                                     a0, a1, a2, a3, wfb.z, wfb.w);
                        }
                    }
                }
            }

            // ==== in-warp transpose epilogue (private scratch, no CTA sync) ====
            float* swp = scratch + wid * (32 * SCRW);
            float* ob  = out + (size_t)b * C_CH * HW;
#pragma unroll
            for (int rr = 0; rr < 2; ++rr) {
                const int oy = by + r0 + rr;
                // STS: conflict-free via XOR-8 swizzle on px for co&4
#pragma unroll
                for (int nt = 0; nt < 4; ++nt) {
#pragma unroll
                    for (int mt = 0; mt < 2; ++mt) {
#pragma unroll
                        for (int e = 0; e < 4; ++e) {
                            int px = m0 + mt * 16 + ((e >> 1) << 3);
                            int co = nt * 8 + cb + (e & 1);
                            swp[co * SCRW + (px ^ ((co & 4) << 1))] = acc[rr][mt][nt][e];
                        }
                    }
                }
                __syncwarp();
                const int co_l = lane >> 3;
                const int P0   = (lane & 7) * 4;
#pragma unroll
                for (int cg = 0; cg < 8; ++cg) {
                    int co = cg * 4 + co_l;
                    int sw = (cg & 1) * 8;
                    float4 v = *(float4*)&swp[co * SCRW + (P0 ^ sw)];
                    float bb = sbias[co];
                    float4 o;
                    o.x = fmaxf(v.x + bb, 0.f);
                    o.y = fmaxf(v.y + bb, 0.f);
                    o.z = fmaxf(v.z + bb, 0.f);
                    o.w = fmaxf(v.w + bb, 0.f);
                    *(float4*)(ob + (size_t)co * HW + (oy << 8) + bx + P0) = o;
                }
                __syncwarp();
            }
        } else if (hasnext) {
            // ============ builder role: tile i+1 into qn (4-deep MLP) ============
            const float* xbn = x + (size_t)nb * C_CH * HW;
            const int g = wid & 3;
            float F[4][8];
            ldrow(xbn, nby, nbx, 0, g, lane, F[0]);
            ldrow(xbn, nby, nbx, 1, g, lane, F[1]);
            ldrow(xbn, nby, nbx, 2, g, lane, F[2]);
            ldrow(xbn, nby, nbx, 3, g, lane, F[3]);
#pragma unroll
            for (int r = 0; r < 10; ++r) {
                strow(qn, nby, r, g, lane, ivr, shr, F[r & 3]);
                if (r + 4 < 10) ldrow(xbn, nby, nbx, r + 4, g, lane, F[r & 3]);
            }
            halo_item(qn, xbn, nby, nbx, g * 32 + lane, sinvf, sshf);
        }

        __syncthreads();
        b = nb; by = nby; bx = nbx;
    }
}

extern "C" void kernel_launch(void* const* d_in, const int* in_sizes, int n_in,
                              void* d_out, int out_size)
{
    const float* x     = (const float*)d_in[0];
    const float* gamma = (const float*)d_in[1];
    const float* beta  = (const float*)d_in[2];
    const float* mean  = (const float*)d_in[3];
    const float* var   = (const float*)d_in[4];
    const float* w     = (const float*)d_in[5];
    const float* bias  = (const float*)d_in[6];
    float* out = (float*)d_out;

    cudaFuncSetAttribute(tbconv_chunk_kernel,
                         cudaFuncAttributeMaxDynamicSharedMemorySize, SMEM_BYTES);

    tbconv_chunk_kernel<<<NCTA, NT, SMEM_BYTES>>>(x, gamma, beta, mean, var, w, bias, out);
}

// round 16
// speedup vs baseline: 1.4304x; 1.4304x over previous
#include <cuda_runtime.h>
#include <cuda_fp16.h>

// ---------------------------------------------------------------------------
// Fused BN -> sign(+-1) -> 3x3 conv -> bias -> ReLU, fp16 tensor-core
// implicit GEMM. Persistent CTAs, warp-specialized (R12 structure + walk):
//   warps 0-3: MMA (2 rows x 32 px x 32 co) + in-warp transpose epilogue
//   warps 4-7: build next tile concurrently.
// R16: k-loop restructured as (S,dx) with dy-dedup of A fragments:
// 4 distinct row-fragments serve 6 (rr,dy) combos -> A-ldsm traffic -33%.
// 2 CTAs/SM. Tile: 8 rows x 32 px x 32 co.
// ---------------------------------------------------------------------------

#define HW      65536
#define C_CH    32

#define QROWS   10           // 8 + 2 halo
#define QPX     34           // 32 + 2 halo
#define CIP     40           // ci stride (halfs) -> 80B px stride, ldsm-safe
#define QTILE   (QROWS * QPX * CIP)   // 13600 halfs
#define NWF4    (9 * 2 * 2 * 32)      // 1152 uint4 weight frag pairs
#define SCRW    40                    // scratch px stride (floats)

#define OFF_Q0  0
#define OFF_Q1  (QTILE * 2)
#define OFF_WF  (QTILE * 4)            // 54400
#define OFF_SI  (OFF_WF + NWF4 * 16)   // 72832 : sinvf float[32]
#define OFF_SS  (OFF_SI + 128)         // sshf  float[32]
#define OFF_SB  (OFF_SS + 128)         // sbias float[32]
#define OFF_SCR (OFF_SB + 128)         // 73344 : 4 warps x 32co x 40 floats
#define SMEM_BYTES (OFF_SCR + 4 * 32 * SCRW * 4)   // 93824

#define NT      256
#define NCTA    296                    // 2 per SM x 148
#define NTILES  4096                   // 16 b x 32 y x 8 x (bx fastest)

__device__ __forceinline__ void ldsm_x4(unsigned &a0, unsigned &a1,
                                        unsigned &a2, unsigned &a3,
                                        unsigned addr) {
    asm volatile("ldmatrix.sync.aligned.m8n8.x4.shared.b16 {%0,%1,%2,%3}, [%4];"
                 : "=r"(a0), "=r"(a1), "=r"(a2), "=r"(a3) : "r"(addr));
}
__device__ __forceinline__ void mma16816(float &c0, float &c1, float &c2, float &c3,
                                         unsigned a0, unsigned a1, unsigned a2, unsigned a3,
                                         unsigned b0, unsigned b1) {
    asm volatile("mma.sync.aligned.m16n8k16.row.col.f32.f16.f16.f32 "
                 "{%0,%1,%2,%3},{%4,%5,%6,%7},{%8,%9},{%0,%1,%2,%3};"
                 : "+f"(c0), "+f"(c1), "+f"(c2), "+f"(c3)
                 : "r"(a0), "r"(a1), "r"(a2), "r"(a3), "r"(b0), "r"(b1));
}
__device__ __forceinline__ unsigned pk2(float f0, float iv0, float sh0,
                                        float f1, float iv1, float sh1, bool ok) {
    unsigned lo = ok ? (fmaf(f0, iv0, sh0) > 0.f ? 0x3C00u : 0xBC00u) : 0u;
    unsigned hi = ok ? (fmaf(f1, iv1, sh1) > 0.f ? 0x3C00u : 0xBC00u) : 0u;
    return lo | (hi << 16);
}
__device__ __forceinline__ void sts128(unsigned addr, uint4 v) {
    asm volatile("st.shared.v4.b32 [%0], {%1,%2,%3,%4};"
                 :: "r"(addr), "r"(v.x), "r"(v.y), "r"(v.z), "r"(v.w));
}

// load one body row-group: 8 ci (group g) x 32 px for stored row r
__device__ __forceinline__ void ldrow(const float* __restrict__ xb,
                                      int by, int bx, int r, int g, int lane,
                                      float* F) {
    int gy = by + r - 1;
    bool ok = (unsigned)gy < 256u;
#pragma unroll
    for (int j = 0; j < 8; ++j) F[j] = 0.f;
    if (ok) {
        const float* p = xb + (size_t)(g * 8) * HW + (gy << 8) + bx + lane;
#pragma unroll
        for (int j = 0; j < 8; ++j) F[j] = __ldg(p + (size_t)j * HW);
    }
}
__device__ __forceinline__ void strow(unsigned qn, int by, int r, int g, int lane,
                                      const float* ivr, const float* shr,
                                      const float* F) {
    bool ok = (unsigned)(by + r - 1) < 256u;
    uint4 v;
    v.x = pk2(F[0], ivr[0], shr[0], F[1], ivr[1], shr[1], ok);
    v.y = pk2(F[2], ivr[2], shr[2], F[3], ivr[3], shr[3], ok);
    v.z = pk2(F[4], ivr[4], shr[4], F[5], ivr[5], shr[5], ok);
    v.w = pk2(F[6], ivr[6], shr[6], F[7], ivr[7], shr[7], ok);
    sts128(qn + (((r * QPX + lane + 1) * CIP + g * 8) << 1), v);
}
// halo item ht in [0,80): (r 0..9, side 0..1, oct 0..3), px 0 or 33
__device__ __forceinline__ void halo_item(unsigned qn, const float* __restrict__ xb,
                                          int by, int bx, int ht,
                                          const float* sinvf, const float* sshf) {
    if (ht >= 80) return;
    int r = ht >> 3, side = (ht >> 2) & 1, oct = ht & 3;
    int px = side ? 33 : 0;
    int gy = by + r - 1, gx = bx + px - 1;
    bool ok = ((unsigned)gy < 256u) & ((unsigned)gx < 256u);
    float f[8];
#pragma unroll
    for (int j = 0; j < 8; ++j) f[j] = 0.f;
    if (ok) {
        const float* p = xb + (size_t)(oct * 8) * HW + (gy << 8) + gx;
#pragma unroll
        for (int j = 0; j < 8; ++j) f[j] = __ldg(p + (size_t)j * HW);
    }
    const float* iv = sinvf + oct * 8;
    const float* sh = sshf + oct * 8;
    uint4 v;
    v.x = pk2(f[0], iv[0], sh[0], f[1], iv[1], sh[1], ok);
    v.y = pk2(f[2], iv[2], sh[2], f[3], iv[3], sh[3], ok);
    v.z = pk2(f[4], iv[4], sh[4], f[5], iv[5], sh[5], ok);
    v.w = pk2(f[6], iv[6], sh[6], f[7], iv[7], sh[7], ok);
    sts128(qn + (((r * QPX + px) * CIP + oct * 8) << 1), v);
}

__global__ __launch_bounds__(NT, 2)
void tbconv_dedup_kernel(const float* __restrict__ x,
                         const float* __restrict__ gamma,
                         const float* __restrict__ beta,
                         const float* __restrict__ mean,
                         const float* __restrict__ var,
                         const float* __restrict__ w,
                         const float* __restrict__ bias,
                         float* __restrict__ out)
{
    extern __shared__ char smraw[];
    uint4* wfragsm = (uint4*)(smraw + OFF_WF);
    float* sinvf   = (float*)(smraw + OFF_SI);
    float* sshf    = (float*)(smraw + OFF_SS);
    float* sbias   = (float*)(smraw + OFF_SB);
    float* scratch = (float*)(smraw + OFF_SCR);   // [warp(4)][co(32)][SCRW]

    const int tid  = threadIdx.x;
    const int lane = tid & 31;
    const int wid  = tid >> 5;

    // ---- one-time setup ----
    if (tid < 32) {
        float inv = gamma[tid] * rsqrtf(var[tid] + 1e-4f);
        sinvf[tid] = inv;
        sshf[tid]  = beta[tid] - mean[tid] * inv;
        sbias[tid] = bias[tid];
    }
    // weights pre-shuffled into mma B-fragment order, nt-paired uint4:
    for (int i = tid; i < NWF4; i += NT) {
        int t = i & 31, np = (i >> 5) & 1, s = (i >> 6) & 1, tap = i >> 7;
        int ci = s * 16 + (t & 3) * 2;
        const float* wb0 = w + ((np * 16 + (t >> 2)) * 32 + ci) * 9 + tap;
        const float* wb1 = wb0 + 8 * 32 * 9;
        __half2 lo0 = __floats2half2_rn(wb0[0],  wb0[9]);
        __half2 hi0 = __floats2half2_rn(wb0[72], wb0[81]);
        __half2 lo1 = __floats2half2_rn(wb1[0],  wb1[9]);
        __half2 hi1 = __floats2half2_rn(wb1[72], wb1[81]);
        uint4 v;
        v.x = *(unsigned*)&lo0; v.y = *(unsigned*)&hi0;
        v.z = *(unsigned*)&lo1; v.w = *(unsigned*)&hi1;
        wfragsm[i] = v;
    }

    const unsigned q0a = (unsigned)__cvta_generic_to_shared(smraw) + OFF_Q0;
    const unsigned q1a = q0a + QTILE * 2;

    const int pxl0 = (lane & 7) + ((lane >> 3) & 1) * 8;
    const int cih  = (lane >> 4) * 8;
    const int m0   = lane >> 2;
    const int cb   = (lane & 3) * 2;

    int cur = blockIdx.x;
    int b  = cur >> 8;
    int by = ((cur >> 3) & 31) << 3;
    int bx = (cur & 7) << 5;

    __syncthreads();   // setup visible

    // BN constants in registers (used by builders)
    float ivr[8], shr[8];
    {
        int g8 = (wid & 3) * 8;
#pragma unroll
        for (int j = 0; j < 8; ++j) { ivr[j] = sinvf[g8 + j]; shr[j] = sshf[g8 + j]; }
    }

    // ---- prologue: ALL 8 warps build tile 0 into q0 ----
    {
        const float* xb = x + (size_t)b * C_CH * HW;
        int g = wid & 3;
        int rbase = (wid >> 2) * 5;
        float F[8];
#pragma unroll
        for (int k = 0; k < 5; ++k) {
            ldrow(xb, by, bx, rbase + k, g, lane, F);
            strow(q0a, by, rbase + k, g, lane, ivr, shr, F);
        }
        halo_item(q0a, xb, by, bx, tid, sinvf, sshf);
    }
    __syncthreads();

    bool flip = false;

    while (cur < NTILES) {
        const unsigned qc = flip ? q1a : q0a;
        const unsigned qn = flip ? q0a : q1a;

        const int nxt = cur + NCTA;
        const bool hasnext = (nxt < NTILES);
        int nb = 0, nby = 0, nbx = 0;
        if (hasnext) {
            nb  = nxt >> 8;
            nby = ((nxt >> 3) & 31) << 3;
            nbx = (nxt & 7) << 5;
        }

        if (wid < 4) {
            // ============ MMA role: 2 rows x 32 px x 32 co ============
            const int r0 = wid * 2;
            float acc[2][2][4][4];
#pragma unroll
            for (int rr = 0; rr < 2; ++rr)
#pragma unroll
                for (int mt = 0; mt < 2; ++mt)
#pragma unroll
                    for (int nt = 0; nt < 4; ++nt)
#pragma unroll
                        for (int k = 0; k < 4; ++k) acc[rr][mt][nt][k] = 0.f;

            // k-loop over (S, dx); A fragments dedup'd across dy:
            // rows r0+0..r0+3 serve all (rr,dy) with arow = rr+dy.
#pragma unroll
            for (int S = 0; S < 2; ++S) {
#pragma unroll
                for (int dx = 0; dx < 3; ++dx) {
                    // W fragments for the 3 taps of this dx column
                    uint4 wfa[3], wfb[3];
#pragma unroll
                    for (int dy = 0; dy < 3; ++dy) {
                        const int tap = dy * 3 + dx;
                        wfa[dy] = wfragsm[(((tap * 2 + S) * 2) + 0) * 32 + lane];
                        wfb[dy] = wfragsm[(((tap * 2 + S) * 2) + 1) * 32 + lane];
                    }
                    // A fragments: 4 distinct rows x 2 mt
                    unsigned af[4][2][4];
#pragma unroll
                    for (int j = 0; j < 4; ++j) {
#pragma unroll
                        for (int mt = 0; mt < 2; ++mt) {
                            unsigned addr = qc +
                                ((((r0 + j) * QPX + mt * 16 + dx + pxl0) * CIP
                                  + cih + S * 16) << 1);
                            ldsm_x4(af[j][mt][0], af[j][mt][1],
                                    af[j][mt][2], af[j][mt][3], addr);
                        }
                    }
                    // 48 mma: rr x dy x mt x 4nt, A row = rr + dy
#pragma unroll
                    for (int dy = 0; dy < 3; ++dy) {
#pragma unroll
                        for (int rr = 0; rr < 2; ++rr) {
                            const int j = rr + dy;
#pragma unroll
                            for (int mt = 0; mt < 2; ++mt) {
                                const unsigned *a = af[j][mt];
                                mma16816(acc[rr][mt][0][0], acc[rr][mt][0][1],
                                         acc[rr][mt][0][2], acc[rr][mt][0][3],
                                         a[0], a[1], a[2], a[3],
                                         wfa[dy].x, wfa[dy].y);
                                mma16816(acc[rr][mt][1][0], acc[rr][mt][1][1],
                                         acc[rr][mt][1][2], acc[rr][mt][1][3],
                                         a[0], a[1], a[2], a[3],
                                         wfa[dy].z, wfa[dy].w);
                                mma16816(acc[rr][mt][2][0], acc[rr][mt][2][1],
                                         acc[rr][mt][2][2], acc[rr][mt][2][3],
                                         a[0], a[1], a[2], a[3],
                                         wfb[dy].x, wfb[dy].y);
                                mma16816(acc[rr][mt][3][0], acc[rr][mt][3][1],
                                         acc[rr][mt][3][2], acc[rr][mt][3][3],
                                         a[0], a[1], a[2], a[3],
                                         wfb[dy].z, wfb[dy].w);
                            }
                        }
                    }
                }
            }

            // ==== in-warp transpose epilogue (private scratch, no CTA sync) ====
            float* swp = scratch + wid * (32 * SCRW);
            float* ob  = out + (size_t)b * C_CH * HW;
#pragma unroll
            for (int rr = 0; rr < 2; ++rr) {
                const int oy = by + r0 + rr;
                // STS: conflict-free via XOR-8 swizzle on px for co&4
#pragma unroll
                for (int nt = 0; nt < 4; ++nt) {
#pragma unroll
                    for (int mt = 0; mt < 2; ++mt) {
#pragma unroll
                        for (int e = 0; e < 4; ++e) {
                            int px = m0 + mt * 16 + ((e >> 1) << 3);
                            int co = nt * 8 + cb + (e & 1);
                            swp[co * SCRW + (px ^ ((co & 4) << 1))] = acc[rr][mt][nt][e];
                        }
                    }
                }
                __syncwarp();
                const int co_l = lane >> 3;
                const int P0   = (lane & 7) * 4;
#pragma unroll
                for (int cg = 0; cg < 8; ++cg) {
                    int co = cg * 4 + co_l;
                    int sw = (cg & 1) * 8;
                    float4 v = *(float4*)&swp[co * SCRW + (P0 ^ sw)];
                    float bb = sbias[co];
                    float4 o;
                    o.x = fmaxf(v.x + bb, 0.f);
                    o.y = fmaxf(v.y + bb, 0.f);
                    o.z = fmaxf(v.z + bb, 0.f);
                    o.w = fmaxf(v.w + bb, 0.f);
                    *(float4*)(ob + (size_t)co * HW + (oy << 8) + bx + P0) = o;
                }
                __syncwarp();
            }
        } else if (hasnext) {
            // ============ builder role: tile i+1 into qn ============
            const float* xbn = x + (size_t)nb * C_CH * HW;
            const int g = wid & 3;
            float FA[8], FB[8];
            ldrow(xbn, nby, nbx, 0, g, lane, FA);
#pragma unroll
            for (int r = 0; r < 10; r += 2) {
                ldrow(xbn, nby, nbx, r + 1, g, lane, FB);
                strow(qn, nby, r, g, lane, ivr, shr, FA);
                if (r + 2 < 10) ldrow(xbn, nby, nbx, r + 2, g, lane, FA);
                strow(qn, nby, r + 1, g, lane, ivr, shr, FB);
            }
            halo_item(qn, xbn, nby, nbx, g * 32 + lane, sinvf, sshf);
        }

        __syncthreads();
        cur = nxt; b = nb; by = nby; bx = nbx;
        flip = !flip;
    }
}

extern "C" void kernel_launch(void* const* d_in, const int* in_sizes, int n_in,
                              void* d_out, int out_size)
{
    const float* x     = (const float*)d_in[0];
    const float* gamma = (const float*)d_in[1];
    const float* beta  = (const float*)d_in[2];
    const float* mean  = (const float*)d_in[3];
    const float* var   = (const float*)d_in[4];
    const float* w     = (const float*)d_in[5];
    const float* bias  = (const float*)d_in[6];
    float* out = (float*)d_out;

    cudaFuncSetAttribute(tbconv_dedup_kernel,
                         cudaFuncAttributeMaxDynamicSharedMemorySize, SMEM_BYTES);

    tbconv_dedup_kernel<<<NCTA, NT, SMEM_BYTES>>>(x, gamma, beta, mean, var, w, bias, out);
}